// round 9
// baseline (speedup 1.0000x reference)
#include <cuda_runtime.h>
#include <cuda_fp16.h>
#include <cstdint>

// x [B=512, T=128, C=512] fp32; Wq/Wk/Wv [H=64, C=512]; out [B, T, 64] fp32.
// 512-thread CTA per batch (16 warps). mma.sync m16n8k16 FP16.
// cp.async double-buffered staging; ldmatrix A-frags in S/PV; balanced causal.
#define TT 128
#define CC 512
#define HH 64
#define KT 32
#define NTH 512

// pitches
#define PTF 40    // staging tiles, fp32 words
#define PQH 72    // Qs/Ks [128][64] half (36 u32, 36%32=4; 144B rows -> ldmatrix ok)
#define PVH 136   // Vt [64][128] half (68 u32)
#define PPH 136   // P  [128][128] half (272B rows -> ldmatrix ok)
#define PSF 132   // S  [128][128] fp32

// smem BYTE offsets
#define OFF_QS  0
#define OFF_KS  18432                       // 128*72*2
#define OFF_VT  36864
#define OFF_SCR 54272                       // +64*136*2
#define OFF_S   OFF_SCR                     // fp32 S (128*132*4 = 67584)
#define OFF_P   (OFF_SCR + 67584)           // half P (128*136*2 = 34816)
#define XBUF(bf) (OFF_SCR + (bf) * 20480)
#define WBUF(bf) (OFF_SCR + 40960 + (bf) * 30720)
#define SMEM_BYTES (OFF_SCR + 40960 + 2 * 30720)   // 156672

__device__ __forceinline__ uint32_t packh(float lo, float hi) {
    __half2 h = __floats2half2_rn(lo, hi);
    return *reinterpret_cast<uint32_t*>(&h);
}
__device__ __forceinline__ uint32_t packh2(float2 v) { return packh(v.x, v.y); }

__device__ __forceinline__ uint32_t smem_u32(const void* p) {
    uint32_t a;
    asm("{ .reg .u64 t; cvta.to.shared.u64 t, %1; cvt.u32.u64 %0, t; }" : "=r"(a) : "l"(p));
    return a;
}
__device__ __forceinline__ void cp16(uint32_t dst, const float* src) {
    asm volatile("cp.async.ca.shared.global [%0], [%1], 16;" :: "r"(dst), "l"(src));
}
#define CP_COMMIT() asm volatile("cp.async.commit_group;" ::: "memory")
#define CP_WAIT1()  asm volatile("cp.async.wait_group 1;"  ::: "memory")
#define CP_WAIT0()  asm volatile("cp.async.wait_group 0;"  ::: "memory")

__device__ __forceinline__ void mma16(float* d, const uint32_t* a, const uint32_t* b) {
    asm volatile(
        "mma.sync.aligned.m16n8k16.row.col.f32.f16.f16.f32 "
        "{%0,%1,%2,%3}, {%4,%5,%6,%7}, {%8,%9}, {%0,%1,%2,%3};"
        : "+f"(d[0]), "+f"(d[1]), "+f"(d[2]), "+f"(d[3])
        : "r"(a[0]), "r"(a[1]), "r"(a[2]), "r"(a[3]), "r"(b[0]), "r"(b[1]));
}
// A-fragment (m16k16) in ONE instruction: 4 m8n8 tiles
#define LDMX4(r, addr) \
    asm volatile("ldmatrix.sync.aligned.m8n8.x4.shared.b16 {%0,%1,%2,%3}, [%4];" \
        : "=r"((r)[0]), "=r"((r)[1]), "=r"((r)[2]), "=r"((r)[3]) : "r"(addr))

__global__ __launch_bounds__(NTH, 1)
void attn_fp16w_kernel(const float* __restrict__ x,
                       const float* __restrict__ Wq,
                       const float* __restrict__ Wk,
                       const float* __restrict__ Wv,
                       float* __restrict__ out)
{
    extern __shared__ char smem[];
    __half* Qs = reinterpret_cast<__half*>(smem + OFF_QS);
    __half* Ks = reinterpret_cast<__half*>(smem + OFF_KS);
    __half* Vt = reinterpret_cast<__half*>(smem + OFF_VT);
    float*  Ss = reinterpret_cast<float*>(smem + OFF_S);
    __half* Ph = reinterpret_cast<__half*>(smem + OFF_P);
    const uint32_t* Kw = reinterpret_cast<const uint32_t*>(smem + OFF_KS);
    const uint32_t* Vw = reinterpret_cast<const uint32_t*>(smem + OFF_VT);
    const uint32_t sb = smem_u32(smem);

    const int tid  = threadIdx.x;
    const int wid  = tid >> 5;
    const int lane = tid & 31;
    const int l4   = lane >> 2;
    const int lk   = lane & 3;
    const int b    = blockIdx.x;
    const float* xb = x + (size_t)b * TT * CC;

    const int wr = wid >> 2;        // 0..3 row-pair group: rows {wr, 7-wr}
    const int wc = wid & 3;         // 0..3 col group
    const int rt0 = wr * 16;
    const int rt1 = (7 - wr) * 16;

    // ldmatrix lane address components
    const int lrow = lane & 7;
    const int radd = ((lane >> 3) & 1) << 3;   // +8 rows for tiles 1,3
    const int kadd = ((lane >> 4) & 1) << 3;   // +8 halves for tiles 2,3

    // --- cp.async tile stagers (raw fp32, pitch 40) ---
    auto issue_chunk = [&](int ch, int bf) {
        const int k0 = ch * KT;
        const uint32_t xB = sb + XBUF(bf);
        const uint32_t wB = sb + WBUF(bf);
#pragma unroll
        for (int q = 0; q < 2; q++) {            // X [128][32] = 1024 float4
            int idx = q * NTH + tid;
            int row = idx >> 3, c4 = idx & 7;
            cp16(xB + (uint32_t)(row * PTF + c4 * 4) * 4, xb + row * CC + k0 + c4 * 4);
        }
#pragma unroll
        for (int q = 0; q < 3; q++) {            // W [192][32] = 1536 float4
            int idx = q * NTH + tid;
            int row = idx >> 3, c4 = idx & 7;
            const float* Wp = (row < 64) ? (Wq + row * CC)
                            : (row < 128) ? (Wk + (row - 64) * CC)
                                          : (Wv + (row - 128) * CC);
            cp16(wB + (uint32_t)(row * PTF + c4 * 4) * 4, Wp + k0 + c4 * 4);
        }
        CP_COMMIT();
    };

    // ============ Phase 1: [Q|K|V] = x @ W^T (16 chunks, double-buffered) ============
    float acc[2][6][4];
#pragma unroll
    for (int i = 0; i < 2; i++)
#pragma unroll
        for (int j = 0; j < 6; j++)
#pragma unroll
            for (int k = 0; k < 4; k++) acc[i][j][k] = 0.0f;

    const int nb1 = wc * 48;     // 6 n-tiles per warp

    issue_chunk(0, 0);
    issue_chunk(1, 1);

#pragma unroll 1
    for (int ch = 0; ch < 16; ch++) {
        if (ch == 15) { CP_WAIT0(); } else { CP_WAIT1(); }
        __syncthreads();
        const int bf = ch & 1;
        const float* Xs  = reinterpret_cast<const float*>(smem + XBUF(bf));
        const float* Wsm = reinterpret_cast<const float*>(smem + WBUF(bf));

#pragma unroll
        for (int ks = 0; ks < 2; ks++) {
            const int kk = ks * 16;
            uint32_t a[2][4];
#pragma unroll
            for (int mt = 0; mt < 2; mt++) {
                const float* ap = Xs + ((mt ? rt1 : rt0) + l4) * PTF + kk + 2 * lk;
                a[mt][0] = packh2(*reinterpret_cast<const float2*>(ap));
                a[mt][1] = packh2(*reinterpret_cast<const float2*>(ap + 8 * PTF));
                a[mt][2] = packh2(*reinterpret_cast<const float2*>(ap + 8));
                a[mt][3] = packh2(*reinterpret_cast<const float2*>(ap + 8 * PTF + 8));
            }
#pragma unroll
            for (int nt = 0; nt < 6; nt++) {
                const float* bp = Wsm + (nb1 + nt * 8 + l4) * PTF + kk + 2 * lk;
                uint32_t b2[2] = { packh2(*reinterpret_cast<const float2*>(bp)),
                                   packh2(*reinterpret_cast<const float2*>(bp + 8)) };
                mma16(acc[0][nt], a[0], b2);
                mma16(acc[1][nt], a[1], b2);
            }
        }
        __syncthreads();
        if (ch < 14) issue_chunk(ch + 2, ch & 1);
    }

    // Epilogue: route D frags to Qs / Ks (half) and Vt (half, transposed)
#pragma unroll
    for (int mt = 0; mt < 2; mt++) {
        const int r0 = (mt ? rt1 : rt0) + l4;
#pragma unroll
        for (int nt = 0; nt < 6; nt++) {
            const int c0 = nb1 + nt * 8 + 2 * lk;
            if (c0 < 64) {
                *reinterpret_cast<uint32_t*>(Qs + r0 * PQH + c0) =
                    packh(acc[mt][nt][0], acc[mt][nt][1]);
                *reinterpret_cast<uint32_t*>(Qs + (r0 + 8) * PQH + c0) =
                    packh(acc[mt][nt][2], acc[mt][nt][3]);
            } else if (c0 < 128) {
                const int c = c0 - 64;
                *reinterpret_cast<uint32_t*>(Ks + r0 * PQH + c) =
                    packh(acc[mt][nt][0], acc[mt][nt][1]);
                *reinterpret_cast<uint32_t*>(Ks + (r0 + 8) * PQH + c) =
                    packh(acc[mt][nt][2], acc[mt][nt][3]);
            } else {
                const int h = c0 - 128;
                Vt[h * PVH + r0]           = __float2half_rn(acc[mt][nt][0]);
                Vt[(h + 1) * PVH + r0]     = __float2half_rn(acc[mt][nt][1]);
                Vt[h * PVH + r0 + 8]       = __float2half_rn(acc[mt][nt][2]);
                Vt[(h + 1) * PVH + r0 + 8] = __float2half_rn(acc[mt][nt][3]);
            }
        }
    }
    __syncthreads();

    // ============ Phase 2: S = Q K^T — balanced causal tiles, ldmatrix A ============
    {
        const int ntmax0 = 2 * wr + 1;
        const int ntmax1 = 15 - 2 * wr;
        // per-lane ldmatrix addresses for Q rows (advance 32B per k16 step)
        uint32_t qa0 = sb + OFF_QS + (uint32_t)(((rt0 + lrow + radd) * PQH + kadd) * 2);
        uint32_t qa1 = sb + OFF_QS + (uint32_t)(((rt1 + lrow + radd) * PQH + kadd) * 2);

        float accS0[4][4], accS1[4][4];
#pragma unroll
        for (int j = 0; j < 4; j++)
#pragma unroll
            for (int k = 0; k < 4; k++) { accS0[j][k] = 0.0f; accS1[j][k] = 0.0f; }

#pragma unroll
        for (int ks = 0; ks < 4; ks++) {
            const int kw = ks * 8 + lk;
            uint32_t a0[4], a1[4];
            LDMX4(a0, qa0 + ks * 32);
            LDMX4(a1, qa1 + ks * 32);
#pragma unroll
            for (int u = 0; u < 4; u++) {
                const int nt = wc + 4 * u;
                if (nt <= ntmax1) {
                    const uint32_t* bp = Kw + (nt * 8 + l4) * 36 + kw;
                    uint32_t b2[2] = { bp[0], bp[4] };
                    mma16(accS1[u], a1, b2);
                    if (nt <= ntmax0) mma16(accS0[u], a0, b2);
                }
            }
        }
#pragma unroll
        for (int u = 0; u < 4; u++) {
            const int nt = wc + 4 * u;
            const int c0 = nt * 8 + 2 * lk;
            if (nt <= ntmax1) {
                const int r0 = rt1 + l4;
                *reinterpret_cast<float2*>(Ss + r0 * PSF + c0) =
                    make_float2(accS1[u][0], accS1[u][1]);
                *reinterpret_cast<float2*>(Ss + (r0 + 8) * PSF + c0) =
                    make_float2(accS1[u][2], accS1[u][3]);
            }
            if (nt <= ntmax0) {
                const int r0 = rt0 + l4;
                *reinterpret_cast<float2*>(Ss + r0 * PSF + c0) =
                    make_float2(accS0[u][0], accS0[u][1]);
                *reinterpret_cast<float2*>(Ss + (r0 + 8) * PSF + c0) =
                    make_float2(accS0[u][2], accS0[u][3]);
            }
        }
    }
    __syncthreads();

    // ============ Softmax (scale + causal mask); P -> half, normalized ============
    {
        for (int rr = 0; rr < 8; rr++) {
            const int r = wid * 8 + rr;
            float v0 = Ss[r * PSF + lane];
            float v1 = Ss[r * PSF + lane + 32];
            float v2 = Ss[r * PSF + lane + 64];
            float v3 = Ss[r * PSF + lane + 96];
            v0 = (lane      <= r) ? v0 * 0.125f : -1e30f;
            v1 = (lane + 32 <= r) ? v1 * 0.125f : -1e30f;
            v2 = (lane + 64 <= r) ? v2 * 0.125f : -1e30f;
            v3 = (lane + 96 <= r) ? v3 * 0.125f : -1e30f;
            float m = fmaxf(fmaxf(v0, v1), fmaxf(v2, v3));
#pragma unroll
            for (int o = 16; o > 0; o >>= 1)
                m = fmaxf(m, __shfl_xor_sync(0xffffffffu, m, o));
            float e0 = __expf(v0 - m), e1 = __expf(v1 - m);
            float e2 = __expf(v2 - m), e3 = __expf(v3 - m);
            float s = e0 + e1 + e2 + e3;
#pragma unroll
            for (int o = 16; o > 0; o >>= 1)
                s += __shfl_xor_sync(0xffffffffu, s, o);
            const float inv = 1.0f / s;
            Ph[r * PPH + lane]      = __float2half_rn(e0 * inv);
            Ph[r * PPH + lane + 32] = __float2half_rn(e1 * inv);
            Ph[r * PPH + lane + 64] = __float2half_rn(e2 * inv);
            Ph[r * PPH + lane + 96] = __float2half_rn(e3 * inv);
        }
    }
    __syncthreads();

    // ============ Phase 3: O = P @ V — ldmatrix A, causal k-skip ============
    {
        const int nb3 = wc * 16;          // 2 n-tiles
        const int ksmax0 = wr;
        const int ksmax1 = 7 - wr;
        uint32_t pa0 = sb + OFF_P + (uint32_t)(((rt0 + lrow + radd) * PPH + kadd) * 2);
        uint32_t pa1 = sb + OFF_P + (uint32_t)(((rt1 + lrow + radd) * PPH + kadd) * 2);

        float accO[2][2][4];
#pragma unroll
        for (int i = 0; i < 2; i++)
#pragma unroll
            for (int j = 0; j < 2; j++)
#pragma unroll
                for (int k = 0; k < 4; k++) accO[i][j][k] = 0.0f;

#pragma unroll
        for (int ks = 0; ks < 8; ks++) {
            if (ks <= ksmax1) {
                const int kw = ks * 8 + lk;
                uint32_t b2[2][2];
#pragma unroll
                for (int nt = 0; nt < 2; nt++) {
                    const uint32_t* bp = Vw + (nb3 + nt * 8 + l4) * 68 + kw;
                    b2[nt][0] = bp[0]; b2[nt][1] = bp[4];
                }
                uint32_t a1[4];
                LDMX4(a1, pa1 + ks * 32);
                mma16(accO[1][0], a1, b2[0]);
                mma16(accO[1][1], a1, b2[1]);
                if (ks <= ksmax0) {
                    uint32_t a0[4];
                    LDMX4(a0, pa0 + ks * 32);
                    mma16(accO[0][0], a0, b2[0]);
                    mma16(accO[0][1], a0, b2[1]);
                }
            }
        }

#pragma unroll
        for (int mt = 0; mt < 2; mt++) {
            const int r0 = (mt ? rt1 : rt0) + l4;
#pragma unroll
            for (int nt = 0; nt < 2; nt++) {
                const int c0 = nb3 + nt * 8 + 2 * lk;
                *reinterpret_cast<float2*>(out + ((size_t)b * TT + r0) * HH + c0) =
                    make_float2(accO[mt][nt][0], accO[mt][nt][1]);
                *reinterpret_cast<float2*>(out + ((size_t)b * TT + r0 + 8) * HH + c0) =
                    make_float2(accO[mt][nt][2], accO[mt][nt][3]);
            }
        }
    }
}

extern "C" void kernel_launch(void* const* d_in, const int* in_sizes, int n_in,
                              void* d_out, int out_size)
{
    const float* x  = (const float*)d_in[0];
    const float* Wq = (const float*)d_in[1];
    const float* Wk = (const float*)d_in[2];
    const float* Wv = (const float*)d_in[3];
    float* out = (float*)d_out;

    const int B = in_sizes[0] / (TT * CC);   // 512

    cudaFuncSetAttribute(attn_fp16w_kernel,
                         cudaFuncAttributeMaxDynamicSharedMemorySize, SMEM_BYTES);
    attn_fp16w_kernel<<<B, NTH, SMEM_BYTES>>>(x, Wq, Wk, Wv, out);
}

// round 10
// speedup vs baseline: 1.1587x; 1.1587x over previous
#include <cuda_runtime.h>
#include <cuda_fp16.h>
#include <cstdint>

// x [B=512, T=128, C=512] fp32; Wq/Wk/Wv [H=64, C=512]; out [B, T, 64] fp32.
// 256-thread CTA per batch. mma.sync m16n8k16 FP16.
// Round-10: W pre-converted to fp16 global once; projection B-frags via
// ldmatrix.x4 (no per-use cvt, half the W smem/L2 bytes). Attention = round 8.
#define TT 128
#define CC 512
#define HH 64
#define KT 32

// pitches
#define PTF 40    // X staging, fp32 words
#define PWH 40    // W staging, halves (80B rows: 16B-aligned, ldmatrix conflict-free)
#define PQH 72    // Qs/Ks [128][64] half
#define PVH 136   // Vt [64][128] half
#define PPH 136   // P  [128][128] half
#define PSF 132   // S  [128][128] fp32

// smem BYTE offsets
#define OFF_QS  0
#define OFF_KS  18432
#define OFF_VT  36864
#define OFF_SCR 54272
#define OFF_S   OFF_SCR                     // fp32 S (67584 B)
#define OFF_P   (OFF_SCR + 67584)           // half P (34816 B)
#define XBUF(bf) (OFF_SCR + (bf) * 20480)               // 2 x 128*40*4
#define WBH(bf)  (OFF_SCR + 40960 + (bf) * 15360)       // 2 x 192*40*2
#define SMEM_BYTES (OFF_SCR + 67584 + 34816)            // 156672 (staging aliases S+P)

__device__ __half Whg[192 * 512];   // fp16 W scratch (Wq|Wk|Wv rows)

__device__ __forceinline__ uint32_t packh(float lo, float hi) {
    __half2 h = __floats2half2_rn(lo, hi);
    return *reinterpret_cast<uint32_t*>(&h);
}
__device__ __forceinline__ uint32_t packh2(float2 v) { return packh(v.x, v.y); }

__device__ __forceinline__ uint32_t smem_u32(const void* p) {
    uint32_t a;
    asm("{ .reg .u64 t; cvta.to.shared.u64 t, %1; cvt.u32.u64 %0, t; }" : "=r"(a) : "l"(p));
    return a;
}
__device__ __forceinline__ void cp16(uint32_t dst, const void* src) {
    asm volatile("cp.async.ca.shared.global [%0], [%1], 16;" :: "r"(dst), "l"(src));
}
#define CP_COMMIT() asm volatile("cp.async.commit_group;" ::: "memory")
#define CP_WAIT1()  asm volatile("cp.async.wait_group 1;"  ::: "memory")
#define CP_WAIT0()  asm volatile("cp.async.wait_group 0;"  ::: "memory")

__device__ __forceinline__ void mma16(float* d, const uint32_t* a, const uint32_t* b) {
    asm volatile(
        "mma.sync.aligned.m16n8k16.row.col.f32.f16.f16.f32 "
        "{%0,%1,%2,%3}, {%4,%5,%6,%7}, {%8,%9}, {%0,%1,%2,%3};"
        : "+f"(d[0]), "+f"(d[1]), "+f"(d[2]), "+f"(d[3])
        : "r"(a[0]), "r"(a[1]), "r"(a[2]), "r"(a[3]), "r"(b[0]), "r"(b[1]));
}
#define LDMX4(r, addr) \
    asm volatile("ldmatrix.sync.aligned.m8n8.x4.shared.b16 {%0,%1,%2,%3}, [%4];" \
        : "=r"((r)[0]), "=r"((r)[1]), "=r"((r)[2]), "=r"((r)[3]) : "r"(addr))

// ------- pre-kernel: W fp32 -> fp16 global -------
__global__ void convw_kernel(const float* __restrict__ Wq,
                             const float* __restrict__ Wk,
                             const float* __restrict__ Wv)
{
    const int row = blockIdx.x;          // 0..191
    const float* Wp = (row < 64) ? (Wq + row * CC)
                    : (row < 128) ? (Wk + (row - 64) * CC)
                                  : (Wv + (row - 128) * CC);
    uint32_t* dst = reinterpret_cast<uint32_t*>(Whg) + row * (CC / 2);
    for (int c = threadIdx.x; c < CC / 2; c += blockDim.x)
        dst[c] = packh2(reinterpret_cast<const float2*>(Wp)[c]);
}

__global__ __launch_bounds__(256, 1)
void attn_fp16b_kernel(const float* __restrict__ x, float* __restrict__ out)
{
    extern __shared__ char smem[];
    __half* Qs = reinterpret_cast<__half*>(smem + OFF_QS);
    __half* Ks = reinterpret_cast<__half*>(smem + OFF_KS);
    __half* Vt = reinterpret_cast<__half*>(smem + OFF_VT);
    float*  Ss = reinterpret_cast<float*>(smem + OFF_S);
    __half* Ph = reinterpret_cast<__half*>(smem + OFF_P);
    const uint32_t* Qw = reinterpret_cast<const uint32_t*>(smem + OFF_QS);
    const uint32_t* Kw = reinterpret_cast<const uint32_t*>(smem + OFF_KS);
    const uint32_t* Vw = reinterpret_cast<const uint32_t*>(smem + OFF_VT);
    const uint32_t* Pw = reinterpret_cast<const uint32_t*>(smem + OFF_P);
    const uint32_t sb = smem_u32(smem);

    const int tid  = threadIdx.x;
    const int wid  = tid >> 5;
    const int lane = tid & 31;
    const int l4   = lane >> 2;
    const int lk   = lane & 3;
    const int b    = blockIdx.x;
    const float* xb = x + (size_t)b * TT * CC;

    const int wr = wid >> 1;        // 0..3
    const int wc = wid & 1;         // 0..1
    const int rt0 = wr * 16;        // row tiles {wr, 7-wr}
    const int rt1 = (7 - wr) * 16;

    // ldmatrix per-lane row offset into W tiles (halves):
    // lanes 0-7: rows n0..n0+7 @k, 8-15: same rows @k+8, 16-23: rows n0+8.. @k,
    // 24-31: rows n0+8.. @k+8  -> x4 = B-frags of two consecutive n-tiles.
    const int wlrow = ((lane & 7) + ((lane >> 4) << 3)) * PWH + (((lane >> 3) & 1) << 3);

    // --- cp.async tile stagers ---
    auto issue_chunk = [&](int ch, int bf) {
        const int k0 = ch * KT;
        const uint32_t xB = sb + XBUF(bf);
        const uint32_t wB = sb + WBH(bf);
#pragma unroll
        for (int q = 0; q < 4; q++) {            // X [128][32] fp32 = 1024 f4
            int idx = q * 256 + tid;
            int row = idx >> 3, c4 = idx & 7;
            cp16(xB + (uint32_t)(row * PTF + c4 * 4) * 4, xb + row * CC + k0 + c4 * 4);
        }
#pragma unroll
        for (int q = 0; q < 3; q++) {            // W [192][32] half = 768 x 16B
            int idx = q * 256 + tid;
            int row = idx >> 2, c8 = idx & 3;
            cp16(wB + (uint32_t)(row * PWH + c8 * 8) * 2,
                 Whg + (size_t)row * CC + k0 + c8 * 8);
        }
        CP_COMMIT();
    };

    // ============ Phase 1: [Q|K|V] = x @ W^T (16 chunks, double-buffered) ============
    float acc[2][12][4];
#pragma unroll
    for (int i = 0; i < 2; i++)
#pragma unroll
        for (int j = 0; j < 12; j++)
#pragma unroll
            for (int k = 0; k < 4; k++) acc[i][j][k] = 0.0f;

    const int nb1 = wc * 96;

    issue_chunk(0, 0);
    issue_chunk(1, 1);

#pragma unroll 1
    for (int ch = 0; ch < 16; ch++) {
        if (ch == 15) { CP_WAIT0(); } else { CP_WAIT1(); }
        __syncthreads();
        const int bf = ch & 1;
        const float* Xs = reinterpret_cast<const float*>(smem + XBUF(bf));
        const uint32_t wBase = sb + WBH(bf) + (uint32_t)(nb1 * PWH + wlrow) * 2;

#pragma unroll
        for (int ks = 0; ks < 2; ks++) {
            const int kk = ks * 16;
            uint32_t a[2][4];
#pragma unroll
            for (int mt = 0; mt < 2; mt++) {
                const float* ap = Xs + ((mt ? rt1 : rt0) + l4) * PTF + kk + 2 * lk;
                a[mt][0] = packh2(*reinterpret_cast<const float2*>(ap));
                a[mt][1] = packh2(*reinterpret_cast<const float2*>(ap + 8 * PTF));
                a[mt][2] = packh2(*reinterpret_cast<const float2*>(ap + 8));
                a[mt][3] = packh2(*reinterpret_cast<const float2*>(ap + 8 * PTF + 8));
            }
#pragma unroll
            for (int p = 0; p < 6; p++) {        // 2 n-tiles per ldmatrix.x4
                uint32_t r[4];
                LDMX4(r, wBase + (uint32_t)(p * 16 * PWH + kk) * 2);
                mma16(acc[0][2 * p],     a[0], r);
                mma16(acc[0][2 * p + 1], a[0], r + 2);
                mma16(acc[1][2 * p],     a[1], r);
                mma16(acc[1][2 * p + 1], a[1], r + 2);
            }
        }
        __syncthreads();
        if (ch < 14) issue_chunk(ch + 2, ch & 1);
    }

    // Epilogue: route D frags to Qs / Ks (half) and Vt (half, transposed)
#pragma unroll
    for (int mt = 0; mt < 2; mt++) {
        const int r0 = (mt ? rt1 : rt0) + l4;
#pragma unroll
        for (int nt = 0; nt < 12; nt++) {
            const int c0 = nb1 + nt * 8 + 2 * lk;
            if (c0 < 64) {
                *reinterpret_cast<uint32_t*>(Qs + r0 * PQH + c0) =
                    packh(acc[mt][nt][0], acc[mt][nt][1]);
                *reinterpret_cast<uint32_t*>(Qs + (r0 + 8) * PQH + c0) =
                    packh(acc[mt][nt][2], acc[mt][nt][3]);
            } else if (c0 < 128) {
                const int c = c0 - 64;
                *reinterpret_cast<uint32_t*>(Ks + r0 * PQH + c) =
                    packh(acc[mt][nt][0], acc[mt][nt][1]);
                *reinterpret_cast<uint32_t*>(Ks + (r0 + 8) * PQH + c) =
                    packh(acc[mt][nt][2], acc[mt][nt][3]);
            } else {
                const int h = c0 - 128;
                Vt[h * PVH + r0]           = __float2half_rn(acc[mt][nt][0]);
                Vt[(h + 1) * PVH + r0]     = __float2half_rn(acc[mt][nt][1]);
                Vt[h * PVH + r0 + 8]       = __float2half_rn(acc[mt][nt][2]);
                Vt[(h + 1) * PVH + r0 + 8] = __float2half_rn(acc[mt][nt][3]);
            }
        }
    }
    __syncthreads();

    // ============ Phase 2: S = Q K^T — balanced causal tiles ============
    {
        const int ntmax0 = 2 * wr + 1;
        const int ntmax1 = 15 - 2 * wr;
        float accS0[8][4], accS1[8][4];
#pragma unroll
        for (int j = 0; j < 8; j++)
#pragma unroll
            for (int k = 0; k < 4; k++) { accS0[j][k] = 0.0f; accS1[j][k] = 0.0f; }

#pragma unroll
        for (int ks = 0; ks < 4; ks++) {
            const int kw = ks * 8 + lk;
            uint32_t a0[4], a1[4];
            {
                const uint32_t* ap = Qw + (rt0 + l4) * 36 + kw;
                a0[0] = ap[0]; a0[1] = ap[36 * 8];
                a0[2] = ap[4]; a0[3] = ap[36 * 8 + 4];
            }
            {
                const uint32_t* ap = Qw + (rt1 + l4) * 36 + kw;
                a1[0] = ap[0]; a1[1] = ap[36 * 8];
                a1[2] = ap[4]; a1[3] = ap[36 * 8 + 4];
            }
#pragma unroll
            for (int u = 0; u < 8; u++) {
                const int nt = wc + 2 * u;
                if (nt <= ntmax1) {
                    const uint32_t* bp = Kw + (nt * 8 + l4) * 36 + kw;
                    uint32_t b2[2] = { bp[0], bp[4] };
                    mma16(accS1[u], a1, b2);
                    if (nt <= ntmax0) mma16(accS0[u], a0, b2);
                }
            }
        }
#pragma unroll
        for (int u = 0; u < 8; u++) {
            const int nt = wc + 2 * u;
            const int c0 = nt * 8 + 2 * lk;
            if (nt <= ntmax1) {
                const int r0 = rt1 + l4;
                *reinterpret_cast<float2*>(Ss + r0 * PSF + c0) =
                    make_float2(accS1[u][0], accS1[u][1]);
                *reinterpret_cast<float2*>(Ss + (r0 + 8) * PSF + c0) =
                    make_float2(accS1[u][2], accS1[u][3]);
            }
            if (nt <= ntmax0) {
                const int r0 = rt0 + l4;
                *reinterpret_cast<float2*>(Ss + r0 * PSF + c0) =
                    make_float2(accS0[u][0], accS0[u][1]);
                *reinterpret_cast<float2*>(Ss + (r0 + 8) * PSF + c0) =
                    make_float2(accS0[u][2], accS0[u][3]);
            }
        }
    }
    __syncthreads();

    // ============ Softmax (scale + causal mask); P -> half, normalized ============
    {
        for (int rr = 0; rr < 16; rr++) {
            const int r = wid * 16 + rr;
            float v0 = Ss[r * PSF + lane];
            float v1 = Ss[r * PSF + lane + 32];
            float v2 = Ss[r * PSF + lane + 64];
            float v3 = Ss[r * PSF + lane + 96];
            v0 = (lane      <= r) ? v0 * 0.125f : -1e30f;
            v1 = (lane + 32 <= r) ? v1 * 0.125f : -1e30f;
            v2 = (lane + 64 <= r) ? v2 * 0.125f : -1e30f;
            v3 = (lane + 96 <= r) ? v3 * 0.125f : -1e30f;
            float m = fmaxf(fmaxf(v0, v1), fmaxf(v2, v3));
#pragma unroll
            for (int o = 16; o > 0; o >>= 1)
                m = fmaxf(m, __shfl_xor_sync(0xffffffffu, m, o));
            float e0 = __expf(v0 - m), e1 = __expf(v1 - m);
            float e2 = __expf(v2 - m), e3 = __expf(v3 - m);
            float s = e0 + e1 + e2 + e3;
#pragma unroll
            for (int o = 16; o > 0; o >>= 1)
                s += __shfl_xor_sync(0xffffffffu, s, o);
            const float inv = 1.0f / s;
            Ph[r * PPH + lane]      = __float2half_rn(e0 * inv);
            Ph[r * PPH + lane + 32] = __float2half_rn(e1 * inv);
            Ph[r * PPH + lane + 64] = __float2half_rn(e2 * inv);
            Ph[r * PPH + lane + 96] = __float2half_rn(e3 * inv);
        }
    }
    __syncthreads();

    // ============ Phase 3: O = P @ V — causal k-skip ============
    {
        const int nb3 = wc * 32;
        const int ksmax0 = wr;
        const int ksmax1 = 7 - wr;
        float accO[2][4][4];
#pragma unroll
        for (int i = 0; i < 2; i++)
#pragma unroll
            for (int j = 0; j < 4; j++)
#pragma unroll
                for (int k = 0; k < 4; k++) accO[i][j][k] = 0.0f;

#pragma unroll
        for (int ks = 0; ks < 8; ks++) {
            if (ks <= ksmax1) {
                const int kw = ks * 8 + lk;
                uint32_t b2[4][2];
#pragma unroll
                for (int nt = 0; nt < 4; nt++) {
                    const uint32_t* bp = Vw + (nb3 + nt * 8 + l4) * 68 + kw;
                    b2[nt][0] = bp[0]; b2[nt][1] = bp[4];
                }
                uint32_t a1[4];
                {
                    const uint32_t* ap = Pw + (rt1 + l4) * 68 + kw;
                    a1[0] = ap[0]; a1[1] = ap[68 * 8];
                    a1[2] = ap[4]; a1[3] = ap[68 * 8 + 4];
                }
#pragma unroll
                for (int nt = 0; nt < 4; nt++) mma16(accO[1][nt], a1, b2[nt]);
                if (ks <= ksmax0) {
                    uint32_t a0[4];
                    const uint32_t* ap = Pw + (rt0 + l4) * 68 + kw;
                    a0[0] = ap[0]; a0[1] = ap[68 * 8];
                    a0[2] = ap[4]; a0[3] = ap[68 * 8 + 4];
#pragma unroll
                    for (int nt = 0; nt < 4; nt++) mma16(accO[0][nt], a0, b2[nt]);
                }
            }
        }

#pragma unroll
        for (int mt = 0; mt < 2; mt++) {
            const int r0 = (mt ? rt1 : rt0) + l4;
#pragma unroll
            for (int nt = 0; nt < 4; nt++) {
                const int c0 = nb3 + nt * 8 + 2 * lk;
                *reinterpret_cast<float2*>(out + ((size_t)b * TT + r0) * HH + c0) =
                    make_float2(accO[mt][nt][0], accO[mt][nt][1]);
                *reinterpret_cast<float2*>(out + ((size_t)b * TT + r0 + 8) * HH + c0) =
                    make_float2(accO[mt][nt][2], accO[mt][nt][3]);
            }
        }
    }
}

extern "C" void kernel_launch(void* const* d_in, const int* in_sizes, int n_in,
                              void* d_out, int out_size)
{
    const float* x  = (const float*)d_in[0];
    const float* Wq = (const float*)d_in[1];
    const float* Wk = (const float*)d_in[2];
    const float* Wv = (const float*)d_in[3];
    float* out = (float*)d_out;

    const int B = in_sizes[0] / (TT * CC);   // 512

    convw_kernel<<<192, 256>>>(Wq, Wk, Wv);

    cudaFuncSetAttribute(attn_fp16b_kernel,
                         cudaFuncAttributeMaxDynamicSharedMemorySize, SMEM_BYTES);
    attn_fp16b_kernel<<<B, 256, SMEM_BYTES>>>(x, out);
}

// round 11
// speedup vs baseline: 1.1648x; 1.0053x over previous
#include <cuda_runtime.h>
#include <cuda_fp16.h>
#include <cstdint>

// x [B=512, T=128, C=512] fp32; Wq/Wk/Wv [H=64, C=512]; out [B, T, 64] fp32.
// 256-thread CTA per batch, 2 CTAs/SM. mma.sync m16n8k16 FP16.
// Round-11: in-register softmax (no fp32 S matrix), KT=16 staging, smem 97KB.
#define TT 128
#define CC 512
#define HH 64
#define KT 16

// pitches
#define PTX 24    // X staging fp32 words (conflict-free LDS.64 per half-warp)
#define PWH 24    // W staging halves (48B rows; ldmatrix 3i%8 permutation)
#define PQH 72    // Qs/Ks [128][64] half
#define PVH 136   // Vt [64][128] half
#define PPH 136   // P  [128][128] half

// smem BYTE offsets
#define OFF_QS  0
#define OFF_KS  18432
#define OFF_VT  36864                        // 64*136*2 = 17408
#define OFF_RED 54272                        // pmax 1024 + psum 1024
#define OFF_SCR 56320
#define OFF_P   OFF_SCR                      // P aliases dead staging (34816)
#define XBUF(bf) (OFF_SCR + (bf) * 12288)    // 2 x 128*24*4
#define WBUF(bf) (OFF_SCR + 24576 + (bf) * 9216)  // 2 x 192*24*2
#define SMEM_BYTES (OFF_SCR + 24576 + 2 * 9216)   // 99328

__device__ __half Whg[192 * 512];   // fp16 W (Wq|Wk|Wv rows), filled by pre-kernel

__device__ __forceinline__ uint32_t packh(float lo, float hi) {
    __half2 h = __floats2half2_rn(lo, hi);
    return *reinterpret_cast<uint32_t*>(&h);
}
__device__ __forceinline__ uint32_t packh2(float2 v) { return packh(v.x, v.y); }

__device__ __forceinline__ uint32_t smem_u32(const void* p) {
    uint32_t a;
    asm("{ .reg .u64 t; cvta.to.shared.u64 t, %1; cvt.u32.u64 %0, t; }" : "=r"(a) : "l"(p));
    return a;
}
__device__ __forceinline__ void cp16(uint32_t dst, const void* src) {
    asm volatile("cp.async.ca.shared.global [%0], [%1], 16;" :: "r"(dst), "l"(src));
}
#define CP_COMMIT() asm volatile("cp.async.commit_group;" ::: "memory")
#define CP_WAIT1()  asm volatile("cp.async.wait_group 1;"  ::: "memory")
#define CP_WAIT0()  asm volatile("cp.async.wait_group 0;"  ::: "memory")

__device__ __forceinline__ void mma16(float* d, const uint32_t* a, const uint32_t* b) {
    asm volatile(
        "mma.sync.aligned.m16n8k16.row.col.f32.f16.f16.f32 "
        "{%0,%1,%2,%3}, {%4,%5,%6,%7}, {%8,%9}, {%0,%1,%2,%3};"
        : "+f"(d[0]), "+f"(d[1]), "+f"(d[2]), "+f"(d[3])
        : "r"(a[0]), "r"(a[1]), "r"(a[2]), "r"(a[3]), "r"(b[0]), "r"(b[1]));
}
#define LDMX4(r, addr) \
    asm volatile("ldmatrix.sync.aligned.m8n8.x4.shared.b16 {%0,%1,%2,%3}, [%4];" \
        : "=r"((r)[0]), "=r"((r)[1]), "=r"((r)[2]), "=r"((r)[3]) : "r"(addr))

// ------- pre-kernel: W fp32 -> fp16 global -------
__global__ void convw_kernel(const float* __restrict__ Wq,
                             const float* __restrict__ Wk,
                             const float* __restrict__ Wv)
{
    const int row = blockIdx.x;          // 0..191
    const float* Wp = (row < 64) ? (Wq + row * CC)
                    : (row < 128) ? (Wk + (row - 64) * CC)
                                  : (Wv + (row - 128) * CC);
    uint32_t* dst = reinterpret_cast<uint32_t*>(Whg) + row * (CC / 2);
    for (int c = threadIdx.x; c < CC / 2; c += blockDim.x)
        dst[c] = packh2(reinterpret_cast<const float2*>(Wp)[c]);
}

__global__ __launch_bounds__(256, 2)
void attn_fp16c_kernel(const float* __restrict__ x, float* __restrict__ out)
{
    extern __shared__ char smem[];
    __half* Qs = reinterpret_cast<__half*>(smem + OFF_QS);
    __half* Ks = reinterpret_cast<__half*>(smem + OFF_KS);
    __half* Vt = reinterpret_cast<__half*>(smem + OFF_VT);
    __half* Ph = reinterpret_cast<__half*>(smem + OFF_P);
    float*  pm = reinterpret_cast<float*>(smem + OFF_RED);        // [2][128] max
    float*  ps = reinterpret_cast<float*>(smem + OFF_RED + 2048); // placed below
    const uint32_t* Qw = reinterpret_cast<const uint32_t*>(smem + OFF_QS);
    const uint32_t* Kw = reinterpret_cast<const uint32_t*>(smem + OFF_KS);
    const uint32_t* Vw = reinterpret_cast<const uint32_t*>(smem + OFF_VT);
    const uint32_t* Pw = reinterpret_cast<const uint32_t*>(smem + OFF_P);
    const uint32_t sb = smem_u32(smem);
    // pmax at OFF_RED (1024B = 2x128 floats), psum right after (1024B)
    ps = reinterpret_cast<float*>(smem + OFF_RED + 1024);

    const int tid  = threadIdx.x;
    const int wid  = tid >> 5;
    const int lane = tid & 31;
    const int l4   = lane >> 2;
    const int lk   = lane & 3;
    const int b    = blockIdx.x;
    const float* xb = x + (size_t)b * TT * CC;

    const int wr = wid >> 1;        // 0..3
    const int wc = wid & 1;         // 0..1
    const int rt0 = wr * 16;        // row tiles {wr, 7-wr}
    const int rt1 = (7 - wr) * 16;

    // ldmatrix per-lane row offset into W staging (halves)
    const int wlrow = ((lane & 7) + ((lane >> 4) << 3)) * PWH + (((lane >> 3) & 1) << 3);

    // --- cp.async tile stagers (KT=16) ---
    auto issue_chunk = [&](int ch, int bf) {
        const int k0 = ch * KT;
        const uint32_t xB = sb + XBUF(bf);
        const uint32_t wB = sb + WBUF(bf);
#pragma unroll
        for (int q = 0; q < 2; q++) {            // X [128][16] fp32 = 512 f4
            int idx = q * 256 + tid;
            int row = idx >> 2, c4 = idx & 3;
            cp16(xB + (uint32_t)(row * PTX + c4 * 4) * 4, xb + row * CC + k0 + c4 * 4);
        }
        {                                         // W [192][16] half = 384 x 16B
            int idx = tid;                        // 256 threads: idx<384 in 2 passes
#pragma unroll
            for (int q = 0; q < 2; q++) {
                int id2 = q * 256 + idx;
                if (id2 < 384) {
                    int row = id2 >> 1, c8 = id2 & 1;
                    cp16(wB + (uint32_t)(row * PWH + c8 * 8) * 2,
                         Whg + (size_t)row * CC + k0 + c8 * 8);
                }
            }
        }
        CP_COMMIT();
    };

    // ============ Phase 1: [Q|K|V] = x @ W^T (32 chunks of k16) ============
    float acc[2][12][4];
#pragma unroll
    for (int i = 0; i < 2; i++)
#pragma unroll
        for (int j = 0; j < 12; j++)
#pragma unroll
            for (int k = 0; k < 4; k++) acc[i][j][k] = 0.0f;

    const int nb1 = wc * 96;

    issue_chunk(0, 0);
    issue_chunk(1, 1);

#pragma unroll 1
    for (int ch = 0; ch < 32; ch++) {
        if (ch == 31) { CP_WAIT0(); } else { CP_WAIT1(); }
        __syncthreads();
        const int bf = ch & 1;
        const float* Xs = reinterpret_cast<const float*>(smem + XBUF(bf));
        const uint32_t wBase = sb + WBUF(bf) + (uint32_t)(nb1 * PWH + wlrow) * 2;

        uint32_t a[2][4];
#pragma unroll
        for (int mt = 0; mt < 2; mt++) {
            const float* ap = Xs + ((mt ? rt1 : rt0) + l4) * PTX + 2 * lk;
            a[mt][0] = packh2(*reinterpret_cast<const float2*>(ap));
            a[mt][1] = packh2(*reinterpret_cast<const float2*>(ap + 8 * PTX));
            a[mt][2] = packh2(*reinterpret_cast<const float2*>(ap + 8));
            a[mt][3] = packh2(*reinterpret_cast<const float2*>(ap + 8 * PTX + 8));
        }
#pragma unroll
        for (int p = 0; p < 6; p++) {            // 2 n-tiles per ldmatrix.x4
            uint32_t r[4];
            LDMX4(r, wBase + (uint32_t)(p * 16 * PWH) * 2);
            mma16(acc[0][2 * p],     a[0], r);
            mma16(acc[0][2 * p + 1], a[0], r + 2);
            mma16(acc[1][2 * p],     a[1], r);
            mma16(acc[1][2 * p + 1], a[1], r + 2);
        }
        __syncthreads();
        if (ch < 30) issue_chunk(ch + 2, ch & 1);
    }

    // Epilogue: route D frags to Qs / Ks (half) and Vt (half, transposed)
#pragma unroll
    for (int mt = 0; mt < 2; mt++) {
        const int r0 = (mt ? rt1 : rt0) + l4;
#pragma unroll
        for (int nt = 0; nt < 12; nt++) {
            const int c0 = nb1 + nt * 8 + 2 * lk;
            if (c0 < 64) {
                *reinterpret_cast<uint32_t*>(Qs + r0 * PQH + c0) =
                    packh(acc[mt][nt][0], acc[mt][nt][1]);
                *reinterpret_cast<uint32_t*>(Qs + (r0 + 8) * PQH + c0) =
                    packh(acc[mt][nt][2], acc[mt][nt][3]);
            } else if (c0 < 128) {
                const int c = c0 - 64;
                *reinterpret_cast<uint32_t*>(Ks + r0 * PQH + c) =
                    packh(acc[mt][nt][0], acc[mt][nt][1]);
                *reinterpret_cast<uint32_t*>(Ks + (r0 + 8) * PQH + c) =
                    packh(acc[mt][nt][2], acc[mt][nt][3]);
            } else {
                const int h = c0 - 128;
                Vt[h * PVH + r0]           = __float2half_rn(acc[mt][nt][0]);
                Vt[(h + 1) * PVH + r0]     = __float2half_rn(acc[mt][nt][1]);
                Vt[h * PVH + r0 + 8]       = __float2half_rn(acc[mt][nt][2]);
                Vt[(h + 1) * PVH + r0 + 8] = __float2half_rn(acc[mt][nt][3]);
            }
        }
    }
    __syncthreads();

    // ============ Phase 2: S = Q K^T + in-register softmax ============
    const int rA0 = rt0 + l4, rB0 = rA0 + 8;
    const int rA1 = rt1 + l4, rB1 = rA1 + 8;
    float invA0, invB0, invA1, invB1;
    {
        const int ntmax0 = 2 * wr + 1;
        const int ntmax1 = 15 - 2 * wr;
        float accS0[8][4], accS1[8][4];
#pragma unroll
        for (int j = 0; j < 8; j++)
#pragma unroll
            for (int k = 0; k < 4; k++) { accS0[j][k] = 0.0f; accS1[j][k] = 0.0f; }

#pragma unroll
        for (int ks = 0; ks < 4; ks++) {
            const int kw = ks * 8 + lk;
            uint32_t a0[4], a1[4];
            {
                const uint32_t* ap = Qw + rA0 * 36 + kw;
                a0[0] = ap[0]; a0[1] = ap[36 * 8];
                a0[2] = ap[4]; a0[3] = ap[36 * 8 + 4];
            }
            {
                const uint32_t* ap = Qw + rA1 * 36 + kw;
                a1[0] = ap[0]; a1[1] = ap[36 * 8];
                a1[2] = ap[4]; a1[3] = ap[36 * 8 + 4];
            }
#pragma unroll
            for (int u = 0; u < 8; u++) {
                const int nt = wc + 2 * u;
                if (nt <= ntmax1) {
                    const uint32_t* bp = Kw + (nt * 8 + l4) * 36 + kw;
                    uint32_t b2[2] = { bp[0], bp[4] };
                    mma16(accS1[u], a1, b2);
                    if (nt <= ntmax0) mma16(accS0[u], a0, b2);
                }
            }
        }

        // mask + scale in registers, partial row maxima
        float mA0 = -1e30f, mB0 = -1e30f, mA1 = -1e30f, mB1 = -1e30f;
#pragma unroll
        for (int u = 0; u < 8; u++) {
            const int c0 = (wc + 2 * u) * 8 + 2 * lk, c1 = c0 + 1;
            accS0[u][0] = (c0 <= rA0) ? accS0[u][0] * 0.125f : -1e30f;
            accS0[u][1] = (c1 <= rA0) ? accS0[u][1] * 0.125f : -1e30f;
            accS0[u][2] = (c0 <= rB0) ? accS0[u][2] * 0.125f : -1e30f;
            accS0[u][3] = (c1 <= rB0) ? accS0[u][3] * 0.125f : -1e30f;
            accS1[u][0] = (c0 <= rA1) ? accS1[u][0] * 0.125f : -1e30f;
            accS1[u][1] = (c1 <= rA1) ? accS1[u][1] * 0.125f : -1e30f;
            accS1[u][2] = (c0 <= rB1) ? accS1[u][2] * 0.125f : -1e30f;
            accS1[u][3] = (c1 <= rB1) ? accS1[u][3] * 0.125f : -1e30f;
            mA0 = fmaxf(mA0, fmaxf(accS0[u][0], accS0[u][1]));
            mB0 = fmaxf(mB0, fmaxf(accS0[u][2], accS0[u][3]));
            mA1 = fmaxf(mA1, fmaxf(accS1[u][0], accS1[u][1]));
            mB1 = fmaxf(mB1, fmaxf(accS1[u][2], accS1[u][3]));
        }
#pragma unroll
        for (int o = 1; o <= 2; o <<= 1) {
            mA0 = fmaxf(mA0, __shfl_xor_sync(0xffffffffu, mA0, o));
            mB0 = fmaxf(mB0, __shfl_xor_sync(0xffffffffu, mB0, o));
            mA1 = fmaxf(mA1, __shfl_xor_sync(0xffffffffu, mA1, o));
            mB1 = fmaxf(mB1, __shfl_xor_sync(0xffffffffu, mB1, o));
        }
        if (lk == 0) {
            pm[wc * 128 + rA0] = mA0; pm[wc * 128 + rB0] = mB0;
            pm[wc * 128 + rA1] = mA1; pm[wc * 128 + rB1] = mB1;
        }
        __syncthreads();
        mA0 = fmaxf(pm[rA0], pm[128 + rA0]);
        mB0 = fmaxf(pm[rB0], pm[128 + rB0]);
        mA1 = fmaxf(pm[rA1], pm[128 + rA1]);
        mB1 = fmaxf(pm[rB1], pm[128 + rB1]);

        // exp, partial sums, write unnormalized P (fp16)
        float sA0 = 0.0f, sB0 = 0.0f, sA1 = 0.0f, sB1 = 0.0f;
#pragma unroll
        for (int u = 0; u < 8; u++) {
            const int c0 = (wc + 2 * u) * 8 + 2 * lk;
            float e0 = __expf(accS0[u][0] - mA0), e1 = __expf(accS0[u][1] - mA0);
            float e2 = __expf(accS0[u][2] - mB0), e3 = __expf(accS0[u][3] - mB0);
            float f0 = __expf(accS1[u][0] - mA1), f1 = __expf(accS1[u][1] - mA1);
            float f2 = __expf(accS1[u][2] - mB1), f3 = __expf(accS1[u][3] - mB1);
            sA0 += e0 + e1; sB0 += e2 + e3;
            sA1 += f0 + f1; sB1 += f2 + f3;
            *reinterpret_cast<uint32_t*>(Ph + rA0 * PPH + c0) = packh(e0, e1);
            *reinterpret_cast<uint32_t*>(Ph + rB0 * PPH + c0) = packh(e2, e3);
            *reinterpret_cast<uint32_t*>(Ph + rA1 * PPH + c0) = packh(f0, f1);
            *reinterpret_cast<uint32_t*>(Ph + rB1 * PPH + c0) = packh(f2, f3);
        }
#pragma unroll
        for (int o = 1; o <= 2; o <<= 1) {
            sA0 += __shfl_xor_sync(0xffffffffu, sA0, o);
            sB0 += __shfl_xor_sync(0xffffffffu, sB0, o);
            sA1 += __shfl_xor_sync(0xffffffffu, sA1, o);
            sB1 += __shfl_xor_sync(0xffffffffu, sB1, o);
        }
        if (lk == 0) {
            ps[wc * 128 + rA0] = sA0; ps[wc * 128 + rB0] = sB0;
            ps[wc * 128 + rA1] = sA1; ps[wc * 128 + rB1] = sB1;
        }
        __syncthreads();     // psum + P visible to all warps
        invA0 = 1.0f / (ps[rA0] + ps[128 + rA0]);
        invB0 = 1.0f / (ps[rB0] + ps[128 + rB0]);
        invA1 = 1.0f / (ps[rA1] + ps[128 + rA1]);
        invB1 = 1.0f / (ps[rB1] + ps[128 + rB1]);
    }

    // ============ Phase 3: O = P @ V — causal k-skip, normalize at store ============
    {
        const int nb3 = wc * 32;
        const int ksmax0 = wr;
        const int ksmax1 = 7 - wr;
        float accO[2][4][4];
#pragma unroll
        for (int i = 0; i < 2; i++)
#pragma unroll
            for (int j = 0; j < 4; j++)
#pragma unroll
                for (int k = 0; k < 4; k++) accO[i][j][k] = 0.0f;

#pragma unroll
        for (int ks = 0; ks < 8; ks++) {
            if (ks <= ksmax1) {
                const int kw = ks * 8 + lk;
                uint32_t b2[4][2];
#pragma unroll
                for (int nt = 0; nt < 4; nt++) {
                    const uint32_t* bp = Vw + (nb3 + nt * 8 + l4) * 68 + kw;
                    b2[nt][0] = bp[0]; b2[nt][1] = bp[4];
                }
                uint32_t a1[4];
                {
                    const uint32_t* ap = Pw + rA1 * 68 + kw;
                    a1[0] = ap[0]; a1[1] = ap[68 * 8];
                    a1[2] = ap[4]; a1[3] = ap[68 * 8 + 4];
                }
#pragma unroll
                for (int nt = 0; nt < 4; nt++) mma16(accO[1][nt], a1, b2[nt]);
                if (ks <= ksmax0) {
                    uint32_t a0[4];
                    const uint32_t* ap = Pw + rA0 * 68 + kw;
                    a0[0] = ap[0]; a0[1] = ap[68 * 8];
                    a0[2] = ap[4]; a0[3] = ap[68 * 8 + 4];
#pragma unroll
                    for (int nt = 0; nt < 4; nt++) mma16(accO[0][nt], a0, b2[nt]);
                }
            }
        }

#pragma unroll
        for (int mt = 0; mt < 2; mt++) {
            const int r0 = (mt ? rA1 : rA0);
            const float ia = mt ? invA1 : invA0;
            const float ib = mt ? invB1 : invB0;
#pragma unroll
            for (int nt = 0; nt < 4; nt++) {
                const int c0 = nb3 + nt * 8 + 2 * lk;
                *reinterpret_cast<float2*>(out + ((size_t)b * TT + r0) * HH + c0) =
                    make_float2(accO[mt][nt][0] * ia, accO[mt][nt][1] * ia);
                *reinterpret_cast<float2*>(out + ((size_t)b * TT + r0 + 8) * HH + c0) =
                    make_float2(accO[mt][nt][2] * ib, accO[mt][nt][3] * ib);
            }
        }
    }
}

extern "C" void kernel_launch(void* const* d_in, const int* in_sizes, int n_in,
                              void* d_out, int out_size)
{
    const float* x  = (const float*)d_in[0];
    const float* Wq = (const float*)d_in[1];
    const float* Wk = (const float*)d_in[2];
    const float* Wv = (const float*)d_in[3];
    float* out = (float*)d_out;

    const int B = in_sizes[0] / (TT * CC);   // 512

    convw_kernel<<<192, 256>>>(Wq, Wk, Wv);

    cudaFuncSetAttribute(attn_fp16c_kernel,
                         cudaFuncAttributeMaxDynamicSharedMemorySize, SMEM_BYTES);
    attn_fp16c_kernel<<<B, 256, SMEM_BYTES>>>(x, out);
}

// round 12
// speedup vs baseline: 1.1949x; 1.0258x over previous
#include <cuda_runtime.h>
#include <cuda_fp16.h>
#include <cstdint>

// x [B=512, T=128, C=512] fp32; Wq/Wk/Wv [H=64, C=512]; out [B, T, 64] fp32.
// Round-12: register-streamed projection (NO cp.async staging, NO mainloop
// barriers). W pre-fragmented to fp16 B-frags in global. 512-thread CTA.
#define TT 128
#define CC 512
#define HH 64
#define NTH 512

#define PQH 72    // Qs/Ks [128][64] half (36 u32 pitch)
#define PVH 136   // Vt [64][128] half  (68 u32 pitch)
#define PPH 136   // P  [128][128] half

#define OFF_QS  0
#define OFF_KS  18432
#define OFF_VT  36864
#define OFF_P   54272
#define OFF_RED 89088            // pmax [4][128] f32 + psum [4][128] f32
#define SMEM_BYTES 93184

// Pre-fragmented fp16 W: Wfg[ch(32)][npair(12)][lane(32)] = uint4
//  {b0(nt=2np), b1(2np), b0(2np+1), b1(2np+1)} for chunk ch (k16).
__device__ uint4 Wfg[32 * 12 * 32];

__device__ __forceinline__ uint32_t packh(float lo, float hi) {
    __half2 h = __floats2half2_rn(lo, hi);
    return *reinterpret_cast<uint32_t*>(&h);
}
__device__ __forceinline__ uint32_t packh2(float2 v) { return packh(v.x, v.y); }

__device__ __forceinline__ void mma16(float* d, const uint32_t* a, const uint32_t* b) {
    asm volatile(
        "mma.sync.aligned.m16n8k16.row.col.f32.f16.f16.f32 "
        "{%0,%1,%2,%3}, {%4,%5,%6,%7}, {%8,%9}, {%0,%1,%2,%3};"
        : "+f"(d[0]), "+f"(d[1]), "+f"(d[2]), "+f"(d[3])
        : "r"(a[0]), "r"(a[1]), "r"(a[2]), "r"(a[3]), "r"(b[0]), "r"(b[1]));
}

// ------- pre-kernel: W fp32 -> fp16 B-fragments in global -------
__global__ void convwf_kernel(const float* __restrict__ Wq,
                              const float* __restrict__ Wk,
                              const float* __restrict__ Wv)
{
    const int blk  = blockIdx.x;        // 0..383 = ch*12 + np
    const int ch   = blk / 12;
    const int np   = blk % 12;
    const int lane = threadIdx.x;       // 32 threads
    const int l4   = lane >> 2;
    const int lk   = lane & 3;
    const int kk   = ch * 16;

    auto wrow = [&](int j) -> const float* {
        return (j < 64) ? (Wq + j * CC)
             : (j < 128) ? (Wk + (j - 64) * CC)
                         : (Wv + (j - 128) * CC);
    };
    const float* r0 = wrow((2 * np) * 8 + l4);
    const float* r1 = wrow((2 * np + 1) * 8 + l4);

    uint4 v;
    v.x = packh2(*reinterpret_cast<const float2*>(r0 + kk + 2 * lk));
    v.y = packh2(*reinterpret_cast<const float2*>(r0 + kk + 2 * lk + 8));
    v.z = packh2(*reinterpret_cast<const float2*>(r1 + kk + 2 * lk));
    v.w = packh2(*reinterpret_cast<const float2*>(r1 + kk + 2 * lk + 8));
    Wfg[blk * 32 + lane] = v;
}

__global__ __launch_bounds__(NTH, 1)
void attn_fp16r_kernel(const float* __restrict__ x, float* __restrict__ out)
{
    extern __shared__ char smem[];
    __half* Qs = reinterpret_cast<__half*>(smem + OFF_QS);
    __half* Ks = reinterpret_cast<__half*>(smem + OFF_KS);
    __half* Vt = reinterpret_cast<__half*>(smem + OFF_VT);
    __half* Ph = reinterpret_cast<__half*>(smem + OFF_P);
    float*  pm = reinterpret_cast<float*>(smem + OFF_RED);          // [4][128]
    float*  ps = reinterpret_cast<float*>(smem + OFF_RED + 2048);   // [4][128]
    const uint32_t* Qw = reinterpret_cast<const uint32_t*>(smem + OFF_QS);
    const uint32_t* Kw = reinterpret_cast<const uint32_t*>(smem + OFF_KS);
    const uint32_t* Vw = reinterpret_cast<const uint32_t*>(smem + OFF_VT);
    const uint32_t* Pw = reinterpret_cast<const uint32_t*>(smem + OFF_P);

    const int tid  = threadIdx.x;
    const int wid  = tid >> 5;
    const int lane = tid & 31;
    const int l4   = lane >> 2;
    const int lk   = lane & 3;
    const int b    = blockIdx.x;
    const float* xb = x + (size_t)b * TT * CC;

    // ---------- Phase 1 ownership: 8 row-tiles x 2 col-halves ----------
    const int rtp = (wid >> 1) * 16;        // row tile (m16)
    const int wcp = wid & 1;                // col half: 96 n-cols
    const int nb1 = wcp * 96;

    float acc[12][4];
#pragma unroll
    for (int j = 0; j < 12; j++)
#pragma unroll
        for (int k = 0; k < 4; k++) acc[j][k] = 0.0f;

    const float* xp0 = xb + (rtp + l4) * CC + 2 * lk;        // row r0
    const float* xp1 = xb + (rtp + 8 + l4) * CC + 2 * lk;    // row r0+8
    const uint4* wfp = Wfg + (wcp * 6) * 32 + lane;          // + ch*12*32

    float2 x0[4], x1[4];
    uint4  w0[6], w1[6];

    auto loadX = [&](int ch, float2* xr) {
        const int kk = ch * 16;
        xr[0] = *reinterpret_cast<const float2*>(xp0 + kk);
        xr[1] = *reinterpret_cast<const float2*>(xp1 + kk);
        xr[2] = *reinterpret_cast<const float2*>(xp0 + kk + 8);
        xr[3] = *reinterpret_cast<const float2*>(xp1 + kk + 8);
    };
    auto loadW = [&](int ch, uint4* wr) {
        const uint4* p = wfp + ch * (12 * 32);
#pragma unroll
        for (int q = 0; q < 6; q++) wr[q] = p[q * 32];
    };
    auto compute = [&](const float2* xr, const uint4* wr) {
        uint32_t a[4] = { packh2(xr[0]), packh2(xr[1]), packh2(xr[2]), packh2(xr[3]) };
#pragma unroll
        for (int p = 0; p < 6; p++) {
            const uint32_t* wp = reinterpret_cast<const uint32_t*>(&wr[p]);
            mma16(acc[2 * p],     a, wp);
            mma16(acc[2 * p + 1], a, wp + 2);
        }
    };

    loadX(0, x0); loadW(0, w0);
    loadX(1, x1); loadW(1, w1);
#pragma unroll 1
    for (int ch = 0; ch < 32; ch += 2) {
        compute(x0, w0);
        if (ch + 2 < 32) { loadX(ch + 2, x0); loadW(ch + 2, w0); }
        compute(x1, w1);
        if (ch + 3 < 32) { loadX(ch + 3, x1); loadW(ch + 3, w1); }
    }

    // Epilogue: route D frags to Qs / Ks (half) and Vt (half, transposed)
    {
        const int r0 = rtp + l4, r1 = r0 + 8;
#pragma unroll
        for (int nt = 0; nt < 12; nt++) {
            const int c0 = nb1 + nt * 8 + 2 * lk;
            float d0 = acc[nt][0], d1 = acc[nt][1], d2 = acc[nt][2], d3 = acc[nt][3];
            if (c0 < 64) {
                *reinterpret_cast<uint32_t*>(Qs + r0 * PQH + c0) = packh(d0, d1);
                *reinterpret_cast<uint32_t*>(Qs + r1 * PQH + c0) = packh(d2, d3);
            } else if (c0 < 128) {
                const int c = c0 - 64;
                *reinterpret_cast<uint32_t*>(Ks + r0 * PQH + c) = packh(d0, d1);
                *reinterpret_cast<uint32_t*>(Ks + r1 * PQH + c) = packh(d2, d3);
            } else {
                const int h = c0 - 128;
                Vt[h * PVH + r0]       = __float2half_rn(d0);
                Vt[(h + 1) * PVH + r0] = __float2half_rn(d1);
                Vt[h * PVH + r1]       = __float2half_rn(d2);
                Vt[(h + 1) * PVH + r1] = __float2half_rn(d3);
            }
        }
    }
    __syncthreads();

    // ---------- Attention ownership: 4 row-pairs x 4 col-groups ----------
    const int wr2 = wid >> 2;               // 0..3 : rows {wr2, 7-wr2}
    const int wc2 = wid & 3;                // 0..3
    const int rt0 = wr2 * 16;
    const int rt1 = (7 - wr2) * 16;
    const int rA0 = rt0 + l4, rB0 = rA0 + 8;
    const int rA1 = rt1 + l4, rB1 = rA1 + 8;
    float invA0, invB0, invA1, invB1;

    // ============ Phase 2: S = Q K^T + in-register softmax ============
    {
        const int ntmax0 = 2 * wr2 + 1;
        const int ntmax1 = 15 - 2 * wr2;
        float accS0[4][4], accS1[4][4];
#pragma unroll
        for (int j = 0; j < 4; j++)
#pragma unroll
            for (int k = 0; k < 4; k++) { accS0[j][k] = 0.0f; accS1[j][k] = 0.0f; }

#pragma unroll
        for (int ks = 0; ks < 4; ks++) {
            const int kw = ks * 8 + lk;
            uint32_t a0[4], a1[4];
            {
                const uint32_t* ap = Qw + rA0 * 36 + kw;
                a0[0] = ap[0]; a0[1] = ap[36 * 8];
                a0[2] = ap[4]; a0[3] = ap[36 * 8 + 4];
            }
            {
                const uint32_t* ap = Qw + rA1 * 36 + kw;
                a1[0] = ap[0]; a1[1] = ap[36 * 8];
                a1[2] = ap[4]; a1[3] = ap[36 * 8 + 4];
            }
#pragma unroll
            for (int u = 0; u < 4; u++) {
                const int nt = wc2 + 4 * u;
                if (nt <= ntmax1) {
                    const uint32_t* bp = Kw + (nt * 8 + l4) * 36 + kw;
                    uint32_t b2[2] = { bp[0], bp[4] };
                    mma16(accS1[u], a1, b2);
                    if (nt <= ntmax0) mma16(accS0[u], a0, b2);
                }
            }
        }

        // mask + scale in registers, partial row maxima
        float mA0 = -1e30f, mB0 = -1e30f, mA1 = -1e30f, mB1 = -1e30f;
#pragma unroll
        for (int u = 0; u < 4; u++) {
            const int c0 = (wc2 + 4 * u) * 8 + 2 * lk, c1 = c0 + 1;
            accS0[u][0] = (c0 <= rA0) ? accS0[u][0] * 0.125f : -1e30f;
            accS0[u][1] = (c1 <= rA0) ? accS0[u][1] * 0.125f : -1e30f;
            accS0[u][2] = (c0 <= rB0) ? accS0[u][2] * 0.125f : -1e30f;
            accS0[u][3] = (c1 <= rB0) ? accS0[u][3] * 0.125f : -1e30f;
            accS1[u][0] = (c0 <= rA1) ? accS1[u][0] * 0.125f : -1e30f;
            accS1[u][1] = (c1 <= rA1) ? accS1[u][1] * 0.125f : -1e30f;
            accS1[u][2] = (c0 <= rB1) ? accS1[u][2] * 0.125f : -1e30f;
            accS1[u][3] = (c1 <= rB1) ? accS1[u][3] * 0.125f : -1e30f;
            mA0 = fmaxf(mA0, fmaxf(accS0[u][0], accS0[u][1]));
            mB0 = fmaxf(mB0, fmaxf(accS0[u][2], accS0[u][3]));
            mA1 = fmaxf(mA1, fmaxf(accS1[u][0], accS1[u][1]));
            mB1 = fmaxf(mB1, fmaxf(accS1[u][2], accS1[u][3]));
        }
#pragma unroll
        for (int o = 1; o <= 2; o <<= 1) {
            mA0 = fmaxf(mA0, __shfl_xor_sync(0xffffffffu, mA0, o));
            mB0 = fmaxf(mB0, __shfl_xor_sync(0xffffffffu, mB0, o));
            mA1 = fmaxf(mA1, __shfl_xor_sync(0xffffffffu, mA1, o));
            mB1 = fmaxf(mB1, __shfl_xor_sync(0xffffffffu, mB1, o));
        }
        if (lk == 0) {
            pm[wc2 * 128 + rA0] = mA0; pm[wc2 * 128 + rB0] = mB0;
            pm[wc2 * 128 + rA1] = mA1; pm[wc2 * 128 + rB1] = mB1;
        }
        __syncthreads();
        mA0 = fmaxf(fmaxf(pm[rA0], pm[128 + rA0]), fmaxf(pm[256 + rA0], pm[384 + rA0]));
        mB0 = fmaxf(fmaxf(pm[rB0], pm[128 + rB0]), fmaxf(pm[256 + rB0], pm[384 + rB0]));
        mA1 = fmaxf(fmaxf(pm[rA1], pm[128 + rA1]), fmaxf(pm[256 + rA1], pm[384 + rA1]));
        mB1 = fmaxf(fmaxf(pm[rB1], pm[128 + rB1]), fmaxf(pm[256 + rB1], pm[384 + rB1]));

        // exp, partial sums, write unnormalized P (fp16)
        float sA0 = 0.0f, sB0 = 0.0f, sA1 = 0.0f, sB1 = 0.0f;
#pragma unroll
        for (int u = 0; u < 4; u++) {
            const int c0 = (wc2 + 4 * u) * 8 + 2 * lk;
            float e0 = __expf(accS0[u][0] - mA0), e1 = __expf(accS0[u][1] - mA0);
            float e2 = __expf(accS0[u][2] - mB0), e3 = __expf(accS0[u][3] - mB0);
            float f0 = __expf(accS1[u][0] - mA1), f1 = __expf(accS1[u][1] - mA1);
            float f2 = __expf(accS1[u][2] - mB1), f3 = __expf(accS1[u][3] - mB1);
            sA0 += e0 + e1; sB0 += e2 + e3;
            sA1 += f0 + f1; sB1 += f2 + f3;
            *reinterpret_cast<uint32_t*>(Ph + rA0 * PPH + c0) = packh(e0, e1);
            *reinterpret_cast<uint32_t*>(Ph + rB0 * PPH + c0) = packh(e2, e3);
            *reinterpret_cast<uint32_t*>(Ph + rA1 * PPH + c0) = packh(f0, f1);
            *reinterpret_cast<uint32_t*>(Ph + rB1 * PPH + c0) = packh(f2, f3);
        }
#pragma unroll
        for (int o = 1; o <= 2; o <<= 1) {
            sA0 += __shfl_xor_sync(0xffffffffu, sA0, o);
            sB0 += __shfl_xor_sync(0xffffffffu, sB0, o);
            sA1 += __shfl_xor_sync(0xffffffffu, sA1, o);
            sB1 += __shfl_xor_sync(0xffffffffu, sB1, o);
        }
        if (lk == 0) {
            ps[wc2 * 128 + rA0] = sA0; ps[wc2 * 128 + rB0] = sB0;
            ps[wc2 * 128 + rA1] = sA1; ps[wc2 * 128 + rB1] = sB1;
        }
        __syncthreads();     // psum + P visible to all warps
        invA0 = 1.0f / (ps[rA0] + ps[128 + rA0] + ps[256 + rA0] + ps[384 + rA0]);
        invB0 = 1.0f / (ps[rB0] + ps[128 + rB0] + ps[256 + rB0] + ps[384 + rB0]);
        invA1 = 1.0f / (ps[rA1] + ps[128 + rA1] + ps[256 + rA1] + ps[384 + rA1]);
        invB1 = 1.0f / (ps[rB1] + ps[128 + rB1] + ps[256 + rB1] + ps[384 + rB1]);
    }

    // ============ Phase 3: O = P @ V — causal k-skip, normalize at store ============
    {
        const int nb3 = wc2 * 16;            // 2 n-tiles of 8 cols
        const int ksmax0 = wr2;
        const int ksmax1 = 7 - wr2;
        float accO[2][2][4];
#pragma unroll
        for (int i = 0; i < 2; i++)
#pragma unroll
            for (int j = 0; j < 2; j++)
#pragma unroll
                for (int k = 0; k < 4; k++) accO[i][j][k] = 0.0f;

#pragma unroll
        for (int ks = 0; ks < 8; ks++) {
            if (ks <= ksmax1) {
                const int kw = ks * 8 + lk;
                uint32_t b2[2][2];
#pragma unroll
                for (int nt = 0; nt < 2; nt++) {
                    const uint32_t* bp = Vw + (nb3 + nt * 8 + l4) * 68 + kw;
                    b2[nt][0] = bp[0]; b2[nt][1] = bp[4];
                }
                uint32_t a1[4];
                {
                    const uint32_t* ap = Pw + rA1 * 68 + kw;
                    a1[0] = ap[0]; a1[1] = ap[68 * 8];
                    a1[2] = ap[4]; a1[3] = ap[68 * 8 + 4];
                }
                mma16(accO[1][0], a1, b2[0]);
                mma16(accO[1][1], a1, b2[1]);
                if (ks <= ksmax0) {
                    uint32_t a0[4];
                    const uint32_t* ap = Pw + rA0 * 68 + kw;
                    a0[0] = ap[0]; a0[1] = ap[68 * 8];
                    a0[2] = ap[4]; a0[3] = ap[68 * 8 + 4];
                    mma16(accO[0][0], a0, b2[0]);
                    mma16(accO[0][1], a0, b2[1]);
                }
            }
        }

#pragma unroll
        for (int mt = 0; mt < 2; mt++) {
            const int r0 = (mt ? rA1 : rA0);
            const float ia = mt ? invA1 : invA0;
            const float ib = mt ? invB1 : invB0;
#pragma unroll
            for (int nt = 0; nt < 2; nt++) {
                const int c0 = nb3 + nt * 8 + 2 * lk;
                *reinterpret_cast<float2*>(out + ((size_t)b * TT + r0) * HH + c0) =
                    make_float2(accO[mt][nt][0] * ia, accO[mt][nt][1] * ia);
                *reinterpret_cast<float2*>(out + ((size_t)b * TT + r0 + 8) * HH + c0) =
                    make_float2(accO[mt][nt][2] * ib, accO[mt][nt][3] * ib);
            }
        }
    }
}

extern "C" void kernel_launch(void* const* d_in, const int* in_sizes, int n_in,
                              void* d_out, int out_size)
{
    const float* x  = (const float*)d_in[0];
    const float* Wq = (const float*)d_in[1];
    const float* Wk = (const float*)d_in[2];
    const float* Wv = (const float*)d_in[3];
    float* out = (float*)d_out;

    const int B = in_sizes[0] / (TT * CC);   // 512

    convwf_kernel<<<384, 32>>>(Wq, Wk, Wv);

    cudaFuncSetAttribute(attn_fp16r_kernel,
                         cudaFuncAttributeMaxDynamicSharedMemorySize, SMEM_BYTES);
    attn_fp16r_kernel<<<B, NTH, SMEM_BYTES>>>(x, out);
}